// round 5
// baseline (speedup 1.0000x reference)
#include <cuda_runtime.h>
#include <cstdint>
#include <cstddef>

#define NN 20000
#define NE 640000
#define EPS 1e-8f

// ------------- device scratch (static, no allocations) -------------
__device__ float    g_aggr[NN * 128];
__device__ float    g_cacc[NN * 3];
__device__ uint32_t g_nft [NN * 128];
__device__ uint32_t g_eW1t[320 * 128];
__device__ uint32_t g_eW2t[128 * 128];
__device__ uint32_t g_nW1t[256 * 128];
__device__ uint32_t g_nW2t[128 * 128];
__device__ uint32_t g_cW1t[128 * 64];

// ------------- helpers -------------
__device__ __forceinline__ uint32_t f2tf(float x) {
    uint32_t u; asm("cvt.rna.tf32.f32 %0, %1;" : "=r"(u) : "f"(x)); return u;
}
__device__ __forceinline__ float silu(float x) { return x / (1.f + __expf(-x)); }

__device__ __forceinline__ void mma8(float* c, const uint32_t* a, uint32_t b0, uint32_t b1) {
    asm volatile(
        "mma.sync.aligned.m16n8k8.row.col.f32.tf32.tf32.f32 "
        "{%0,%1,%2,%3},{%4,%5,%6,%7},{%8,%9},{%0,%1,%2,%3};"
        : "+f"(c[0]), "+f"(c[1]), "+f"(c[2]), "+f"(c[3])
        : "r"(a[0]), "r"(a[1]), "r"(a[2]), "r"(a[3]), "r"(b0), "r"(b1));
}
__device__ __forceinline__ void cpa(void* s, const void* g, bool v) {
    uint32_t sa = (uint32_t)__cvta_generic_to_shared(s);
    int sz = v ? 16 : 0;
    asm volatile("cp.async.cg.shared.global [%0],[%1],16,%2;" :: "r"(sa), "l"(g), "r"(sz));
}
__device__ __forceinline__ void cpcommit() { asm volatile("cp.async.commit_group;"); }
template <int N> __device__ __forceinline__ void cpwait() {
    asm volatile("cp.async.wait_group %0;" :: "n"(N));
}
__device__ __forceinline__ void redv4(float* gp, float x, float y, float z, float w) {
    asm volatile("red.global.add.v4.f32 [%0],{%1,%2,%3,%4};"
                 :: "l"(gp), "f"(x), "f"(y), "f"(z), "f"(w));
}

// smem pitches (words): A-pitch = 4 mod 32, B-pitch = 8 mod 32 -> conflict-free frags
#define PX 36
#define PW 136
#define PH 132
#define PW3 72

// edge kernel smem word offsets
#define OFF_EB1 256
#define OFF_EB2 384
#define OFF_CB1 512
#define OFF_CW2 576
#define OFF_SCW 640
#define OFF_X   768
#define OFF_W   9984
#define OFF_H   18688
#define OFF_M   35584
#define EDGE_SMEM_BYTES (52480 * 4)

// node kernel smem word offsets
#define NOFF_B1 0
#define NOFF_B2 128
#define NOFF_X  256
#define NOFF_W  9472
#define NOFF_H  18176
#define NODE_SMEM_BYTES (35072 * 4)

// ------------- shared GEMM chunk: one 32-wide K slab of a 128xN tile -------------
// warp layout: wm = warp&3 (rows wm*32..+31), wn = warp>>2 (N half)
// acc[2][8][4]: 2 m16 tiles x up-to-8 n8 tiles
template <int NT, bool CVT>
__device__ __forceinline__ void chunk_mma(
    const uint32_t* __restrict__ A, int pa, int acol,
    const uint32_t* __restrict__ W, int pw, int ncb,
    int wm, int g, int tig, float acc[2][8][4])
{
#pragma unroll
    for (int ks = 0; ks < 4; ks++) {
        uint32_t a[2][4];
#pragma unroll
        for (int mt = 0; mt < 2; mt++) {
            int r = wm * 32 + mt * 16 + g;
            const uint32_t* p0 = A + r * pa + acol + ks * 8 + tig;
            const uint32_t* p1 = A + (r + 8) * pa + acol + ks * 8 + tig;
            if (CVT) {
                a[mt][0] = f2tf(__uint_as_float(p0[0]));
                a[mt][1] = f2tf(__uint_as_float(p1[0]));
                a[mt][2] = f2tf(__uint_as_float(p0[4]));
                a[mt][3] = f2tf(__uint_as_float(p1[4]));
            } else {
                a[mt][0] = p0[0]; a[mt][1] = p1[0];
                a[mt][2] = p0[4]; a[mt][3] = p1[4];
            }
        }
        const uint32_t* b0p = W + (ks * 8 + tig) * pw + ncb + g;
        const uint32_t* b1p = W + (ks * 8 + tig + 4) * pw + ncb + g;
#pragma unroll
        for (int nt = 0; nt < NT; nt++) {
            uint32_t b0 = b0p[nt * 8], b1 = b1p[nt * 8];
            mma8(acc[0][nt], a[0], b0, b1);
            mma8(acc[1][nt], a[1], b0, b1);
        }
    }
}

__device__ __forceinline__ void zero_acc(float acc[2][8][4]) {
#pragma unroll
    for (int mt = 0; mt < 2; mt++)
#pragma unroll
        for (int nt = 0; nt < 8; nt++)
#pragma unroll
            for (int q = 0; q < 4; q++) acc[mt][nt][q] = 0.f;
}

__device__ __forceinline__ void load_w_chunk(uint32_t* wb, const uint32_t* Wg,
                                             int wcols, int pw, int kc, int tid) {
    int nv4 = wcols >> 2;
    int tot = 32 * nv4;
    for (int i = tid; i < tot; i += 256) {
        int r = i / nv4, j = i - r * nv4;
        cpa(&wb[r * pw + j * 4], &Wg[(size_t)(kc * 32 + r) * wcols + j * 4], true);
    }
}

// ------------- prep: zero accumulators, pre-convert weights + node_feat -------------
__global__ void prep_k(const float* __restrict__ nf, const float* __restrict__ eW1,
                       const float* __restrict__ eW2, const float* __restrict__ nW1,
                       const float* __restrict__ nW2, const float* __restrict__ cW1) {
    int i = blockIdx.x * 256 + threadIdx.x;
    int st = gridDim.x * 256;
    for (int j = i; j < NN * 128; j += st) { g_aggr[j] = 0.f; g_nft[j] = f2tf(nf[j]); }
    for (int j = i; j < NN * 3; j += st) g_cacc[j] = 0.f;
    for (int j = i; j < 320 * 128; j += st) g_eW1t[j] = f2tf(eW1[j]);
    for (int j = i; j < 128 * 128; j += st) { g_eW2t[j] = f2tf(eW2[j]); g_nW2t[j] = f2tf(nW2[j]); }
    for (int j = i; j < 256 * 128; j += st) g_nW1t[j] = f2tf(nW1[j]);
    for (int j = i; j < 128 * 64; j += st) g_cW1t[j] = f2tf(cW1[j]);
}

// ------------- edge kernel: fully fused edge MLP + scatter + coord head -------------
extern "C" __global__ void __launch_bounds__(256, 1)
edge_kernel(const int* __restrict__ ei, const float* __restrict__ ea,
            const float* __restrict__ coords,
            const float* __restrict__ eb1, const float* __restrict__ eb2,
            const float* __restrict__ cb1, const float* __restrict__ cw2,
            const float* __restrict__ cb2p)
{
    extern __shared__ uint32_t sm[];
    float* smf = (float*)sm;
    int* s_src = (int*)sm;
    int* s_dst = (int*)sm + 128;
    int tid = threadIdx.x;
    int e0 = blockIdx.x * 128;

    if (tid < 128) {
        s_src[tid] = ei[e0 + tid];
        s_dst[tid] = ei[NE + e0 + tid];
        smf[OFF_EB1 + tid] = eb1[tid];
        smf[OFF_EB2 + tid] = eb2[tid];
        smf[OFF_SCW + tid] = 0.f;
    }
    if (tid < 64) { smf[OFF_CB1 + tid] = cb1[tid]; smf[OFF_CW2 + tid] = cw2[tid]; }
    __syncthreads();

    int warp = tid >> 5, lane = tid & 31;
    int wm = warp & 3, wn = warp >> 2;
    int g = lane >> 2, tig = lane & 3;

    // X chunk loader: cols [0,128)=nf[src], [128,256)=nf[dst], [256,320)=edge_attr
    auto loadX = [&](int kc, int buf) {
        uint32_t* xb = sm + OFF_X + buf * (128 * PX);
#pragma unroll
        for (int q = 0; q < 4; q++) {
            int i = q * 256 + tid;
            int row = i >> 3, j = i & 7;
            const float* src;
            if (kc < 4)      src = (const float*)&g_nft[(size_t)s_src[row] * 128 + kc * 32 + j * 4];
            else if (kc < 8) src = (const float*)&g_nft[(size_t)s_dst[row] * 128 + (kc - 4) * 32 + j * 4];
            else             src = &ea[(size_t)(e0 + row) * 64 + (kc - 8) * 32 + j * 4];
            cpa(&xb[row * PX + j * 4], src, true);
        }
    };

    float acc[2][8][4];

    // ================= GEMM1: X[128,320] @ eW1 =================
    zero_acc(acc);
    loadX(0, 0); load_w_chunk(sm + OFF_W, g_eW1t, 128, PW, 0, tid); cpcommit();
    for (int kc = 0; kc < 10; kc++) {
        int cur = kc & 1;
        if (kc < 9) {
            loadX(kc + 1, cur ^ 1);
            load_w_chunk(sm + OFF_W + (cur ^ 1) * (32 * PW), g_eW1t, 128, PW, kc + 1, tid);
            cpcommit(); cpwait<1>();
        } else cpwait<0>();
        __syncthreads();
        chunk_mma<8, false>(sm + OFF_X + cur * (128 * PX), PX, 0,
                            sm + OFF_W + cur * (32 * PW), PW, wn * 64, wm, g, tig, acc);
        __syncthreads();
    }
    // epilogue1: +eb1, silu, tf32 -> H
#pragma unroll
    for (int mt = 0; mt < 2; mt++)
#pragma unroll
        for (int nt = 0; nt < 8; nt++) {
            int r = wm * 32 + mt * 16 + g;
            int c = wn * 64 + nt * 8 + tig * 2;
            float b0 = smf[OFF_EB1 + c], b1 = smf[OFF_EB1 + c + 1];
            sm[OFF_H + r * PH + c]           = f2tf(silu(acc[mt][nt][0] + b0));
            sm[OFF_H + r * PH + c + 1]       = f2tf(silu(acc[mt][nt][1] + b1));
            sm[OFF_H + (r + 8) * PH + c]     = f2tf(silu(acc[mt][nt][2] + b0));
            sm[OFF_H + (r + 8) * PH + c + 1] = f2tf(silu(acc[mt][nt][3] + b1));
        }
    __syncthreads();

    // ================= GEMM2: H[128,128] @ eW2 =================
    zero_acc(acc);
    load_w_chunk(sm + OFF_W, g_eW2t, 128, PW, 0, tid); cpcommit();
    for (int kc = 0; kc < 4; kc++) {
        int cur = kc & 1;
        if (kc < 3) {
            load_w_chunk(sm + OFF_W + (cur ^ 1) * (32 * PW), g_eW2t, 128, PW, kc + 1, tid);
            cpcommit(); cpwait<1>();
        } else cpwait<0>();
        __syncthreads();
        chunk_mma<8, false>(sm + OFF_H, PH, kc * 32,
                            sm + OFF_W + cur * (32 * PW), PW, wn * 64, wm, g, tig, acc);
        __syncthreads();
    }
    // epilogue2: +eb2, silu -> MSG (fp32)
#pragma unroll
    for (int mt = 0; mt < 2; mt++)
#pragma unroll
        for (int nt = 0; nt < 8; nt++) {
            int r = wm * 32 + mt * 16 + g;
            int c = wn * 64 + nt * 8 + tig * 2;
            float b0 = smf[OFF_EB2 + c], b1 = smf[OFF_EB2 + c + 1];
            smf[OFF_M + r * PH + c]           = silu(acc[mt][nt][0] + b0);
            smf[OFF_M + r * PH + c + 1]       = silu(acc[mt][nt][1] + b1);
            smf[OFF_M + (r + 8) * PH + c]     = silu(acc[mt][nt][2] + b0);
            smf[OFF_M + (r + 8) * PH + c + 1] = silu(acc[mt][nt][3] + b1);
        }
    __syncthreads();

    // preload cW1 chunk 0 so its latency hides behind the scatter
    load_w_chunk(sm + OFF_W, g_cW1t, 64, PW3, 0, tid); cpcommit();

    // scatter messages: 16B vector reductions into g_aggr (fire-and-forget)
    for (int i = tid; i < 4096; i += 256) {
        int row = i >> 5, j = (i & 31) * 4;
        const float* mp = &smf[OFF_M + row * PH + j];
        redv4(&g_aggr[(size_t)s_dst[row] * 128 + j], mp[0], mp[1], mp[2], mp[3]);
    }

    // ================= GEMM3: MSG[128,128] @ cW1[128,64] =================
    zero_acc(acc);
    for (int kc = 0; kc < 4; kc++) {
        int cur = kc & 1;
        if (kc < 3) {
            load_w_chunk(sm + OFF_W + (cur ^ 1) * (32 * PW), g_cW1t, 64, PW3, kc + 1, tid);
            cpcommit(); cpwait<1>();
        } else cpwait<0>();
        __syncthreads();
        chunk_mma<4, true>(sm + OFF_M, PH, kc * 32,
                           sm + OFF_W + cur * (32 * PW), PW3, wn * 32, wm, g, tig, acc);
        __syncthreads();
    }
    // coord-head epilogue: cw[row] = sum_c silu(T+cb1)*cW2
    {
        float pa0 = 0.f, pa1 = 0.f, pb0 = 0.f, pb1 = 0.f;
#pragma unroll
        for (int nt = 0; nt < 4; nt++) {
            int c = wn * 32 + nt * 8 + tig * 2;
            float b0 = smf[OFF_CB1 + c], b1 = smf[OFF_CB1 + c + 1];
            float w0 = smf[OFF_CW2 + c], w1 = smf[OFF_CW2 + c + 1];
            pa0 += silu(acc[0][nt][0] + b0) * w0 + silu(acc[0][nt][1] + b1) * w1;
            pa1 += silu(acc[0][nt][2] + b0) * w0 + silu(acc[0][nt][3] + b1) * w1;
            pb0 += silu(acc[1][nt][0] + b0) * w0 + silu(acc[1][nt][1] + b1) * w1;
            pb1 += silu(acc[1][nt][2] + b0) * w0 + silu(acc[1][nt][3] + b1) * w1;
        }
#pragma unroll
        for (int off = 1; off <= 2; off <<= 1) {
            pa0 += __shfl_xor_sync(0xffffffffu, pa0, off);
            pa1 += __shfl_xor_sync(0xffffffffu, pa1, off);
            pb0 += __shfl_xor_sync(0xffffffffu, pb0, off);
            pb1 += __shfl_xor_sync(0xffffffffu, pb1, off);
        }
        if (tig == 0) {
            atomicAdd(&smf[OFF_SCW + wm * 32 + g], pa0);
            atomicAdd(&smf[OFF_SCW + wm * 32 + g + 8], pa1);
            atomicAdd(&smf[OFF_SCW + wm * 32 + 16 + g], pb0);
            atomicAdd(&smf[OFF_SCW + wm * 32 + 16 + g + 8], pb1);
        }
    }
    __syncthreads();

    // coordinate update scatter
    if (tid < 128) {
        float cw = smf[OFF_SCW + tid] + __ldg(cb2p);
        int s = s_src[tid], d = s_dst[tid];
        float dx = __ldg(&coords[s * 3 + 0]) - __ldg(&coords[d * 3 + 0]);
        float dy = __ldg(&coords[s * 3 + 1]) - __ldg(&coords[d * 3 + 1]);
        float dz = __ldg(&coords[s * 3 + 2]) - __ldg(&coords[d * 3 + 2]);
        float sc = cw / (sqrtf(dx * dx + dy * dy + dz * dz) + EPS);
        atomicAdd(&g_cacc[d * 3 + 0], sc * dx);
        atomicAdd(&g_cacc[d * 3 + 1], sc * dy);
        atomicAdd(&g_cacc[d * 3 + 2], sc * dz);
    }
}

// ------------- node kernel: node MLP + residual + coords epilogue -------------
extern "C" __global__ void __launch_bounds__(256, 1)
node_kernel(const float* __restrict__ nf, const float* __restrict__ coords,
            const float* __restrict__ nb1, const float* __restrict__ nb2,
            float* __restrict__ out)
{
    extern __shared__ uint32_t sm[];
    float* smf = (float*)sm;
    int tid = threadIdx.x;
    int n0 = blockIdx.x * 128;

    if (tid < 128) { smf[NOFF_B1 + tid] = nb1[tid]; smf[NOFF_B2 + tid] = nb2[tid]; }
    __syncthreads();

    int warp = tid >> 5, lane = tid & 31;
    int wm = warp & 3, wn = warp >> 2;
    int g = lane >> 2, tig = lane & 3;

    auto loadX = [&](int kc, int buf) {
        uint32_t* xb = sm + NOFF_X + buf * (128 * PX);
#pragma unroll
        for (int q = 0; q < 4; q++) {
            int i = q * 256 + tid;
            int row = i >> 3, j = i & 7;
            int node = n0 + row;
            bool v = node < NN;
            const float* src;
            if (kc < 4) src = (const float*)&g_nft[v ? ((size_t)node * 128 + kc * 32 + j * 4) : 0];
            else        src = &g_aggr[v ? ((size_t)node * 128 + (kc - 4) * 32 + j * 4) : 0];
            cpa(&xb[row * PX + j * 4], src, v);
        }
    };

    float acc[2][8][4];

    // GEMM1: [nf | aggr][128,256] @ nW1
    zero_acc(acc);
    loadX(0, 0); load_w_chunk(sm + NOFF_W, g_nW1t, 128, PW, 0, tid); cpcommit();
    for (int kc = 0; kc < 8; kc++) {
        int cur = kc & 1;
        if (kc < 7) {
            loadX(kc + 1, cur ^ 1);
            load_w_chunk(sm + NOFF_W + (cur ^ 1) * (32 * PW), g_nW1t, 128, PW, kc + 1, tid);
            cpcommit(); cpwait<1>();
        } else cpwait<0>();
        __syncthreads();
        chunk_mma<8, false>(sm + NOFF_X + cur * (128 * PX), PX, 0,
                            sm + NOFF_W + cur * (32 * PW), PW, wn * 64, wm, g, tig, acc);
        __syncthreads();
    }
#pragma unroll
    for (int mt = 0; mt < 2; mt++)
#pragma unroll
        for (int nt = 0; nt < 8; nt++) {
            int r = wm * 32 + mt * 16 + g;
            int c = wn * 64 + nt * 8 + tig * 2;
            float b0 = smf[NOFF_B1 + c], b1 = smf[NOFF_B1 + c + 1];
            sm[NOFF_H + r * PH + c]           = f2tf(silu(acc[mt][nt][0] + b0));
            sm[NOFF_H + r * PH + c + 1]       = f2tf(silu(acc[mt][nt][1] + b1));
            sm[NOFF_H + (r + 8) * PH + c]     = f2tf(silu(acc[mt][nt][2] + b0));
            sm[NOFF_H + (r + 8) * PH + c + 1] = f2tf(silu(acc[mt][nt][3] + b1));
        }
    __syncthreads();

    // GEMM2: H @ nW2
    zero_acc(acc);
    load_w_chunk(sm + NOFF_W, g_nW2t, 128, PW, 0, tid); cpcommit();
    for (int kc = 0; kc < 4; kc++) {
        int cur = kc & 1;
        if (kc < 3) {
            load_w_chunk(sm + NOFF_W + (cur ^ 1) * (32 * PW), g_nW2t, 128, PW, kc + 1, tid);
            cpcommit(); cpwait<1>();
        } else cpwait<0>();
        __syncthreads();
        chunk_mma<8, false>(sm + NOFF_H, PH, kc * 32,
                            sm + NOFF_W + cur * (32 * PW), PW, wn * 64, wm, g, tig, acc);
        __syncthreads();
    }
    // epilogue: residual + bias -> out nodes
#pragma unroll
    for (int mt = 0; mt < 2; mt++)
#pragma unroll
        for (int nt = 0; nt < 8; nt++) {
            int r = wm * 32 + mt * 16 + g;
            int c = wn * 64 + nt * 8 + tig * 2;
            float b0 = smf[NOFF_B2 + c], b1 = smf[NOFF_B2 + c + 1];
            int na = n0 + r, nb = n0 + r + 8;
            if (na < NN) {
                out[(size_t)na * 128 + c]     = acc[mt][nt][0] + b0 + __ldg(&nf[(size_t)na * 128 + c]);
                out[(size_t)na * 128 + c + 1] = acc[mt][nt][1] + b1 + __ldg(&nf[(size_t)na * 128 + c + 1]);
            }
            if (nb < NN) {
                out[(size_t)nb * 128 + c]     = acc[mt][nt][2] + b0 + __ldg(&nf[(size_t)nb * 128 + c]);
                out[(size_t)nb * 128 + c + 1] = acc[mt][nt][3] + b1 + __ldg(&nf[(size_t)nb * 128 + c + 1]);
            }
        }

    // coords epilogue
    for (int i = tid; i < 384; i += 256) {
        int node = n0 + i / 3, k = i % 3;
        if (node < NN)
            out[(size_t)NN * 128 + node * 3 + k] = coords[node * 3 + k] + g_cacc[node * 3 + k];
    }
}

// ------------- host entry -------------
extern "C" void kernel_launch(void* const* d_in, const int* in_sizes, int n_in,
                              void* d_out, int out_size) {
    const float* nf     = (const float*)d_in[0];
    const int*   ei     = (const int*)d_in[1];
    const float* ea     = (const float*)d_in[2];
    const float* coords = (const float*)d_in[3];
    const float* eW1 = (const float*)d_in[4];
    const float* eb1 = (const float*)d_in[5];
    const float* eW2 = (const float*)d_in[6];
    const float* eb2 = (const float*)d_in[7];
    const float* nW1 = (const float*)d_in[8];
    const float* nb1 = (const float*)d_in[9];
    const float* nW2 = (const float*)d_in[10];
    const float* nb2 = (const float*)d_in[11];
    const float* cW1 = (const float*)d_in[12];
    const float* cb1 = (const float*)d_in[13];
    const float* cW2 = (const float*)d_in[14];
    const float* cb2 = (const float*)d_in[15];
    float* out = (float*)d_out;

    cudaFuncSetAttribute(edge_kernel, cudaFuncAttributeMaxDynamicSharedMemorySize, EDGE_SMEM_BYTES);
    cudaFuncSetAttribute(node_kernel, cudaFuncAttributeMaxDynamicSharedMemorySize, NODE_SMEM_BYTES);

    prep_k<<<512, 256>>>(nf, eW1, eW2, nW1, nW2, cW1);
    edge_kernel<<<NE / 128, 256, EDGE_SMEM_BYTES>>>(ei, ea, coords, eb1, eb2, cb1, cW2, cb2);
    node_kernel<<<(NN + 127) / 128, 256, NODE_SMEM_BYTES>>>(nf, coords, nb1, nb2, out);
}

// round 6
// speedup vs baseline: 1.4849x; 1.4849x over previous
#include <cuda_runtime.h>
#include <cstdint>
#include <cstddef>

#define NN 20000
#define NE 640000
#define EPS 1e-8f

// ------------- device scratch (static, no allocations) -------------
__device__ float    g_aggr[NN * 128];
__device__ float    g_cacc[NN * 3];
__device__ uint32_t g_nft [NN * 128];
__device__ uint32_t g_eW1t[320 * 128];
__device__ uint32_t g_eW2t[128 * 128];
__device__ uint32_t g_nW1t[256 * 128];
__device__ uint32_t g_nW2t[128 * 128];
__device__ uint32_t g_cW1t[128 * 64];

// ------------- helpers -------------
__device__ __forceinline__ uint32_t f2tf(float x) {
    uint32_t u; asm("cvt.rna.tf32.f32 %0, %1;" : "=r"(u) : "f"(x)); return u;
}
__device__ __forceinline__ float silu(float x) { return x / (1.f + __expf(-x)); }

__device__ __forceinline__ void mma8(float* c, const uint32_t* a, uint32_t b0, uint32_t b1) {
    asm volatile(
        "mma.sync.aligned.m16n8k8.row.col.f32.tf32.tf32.f32 "
        "{%0,%1,%2,%3},{%4,%5,%6,%7},{%8,%9},{%0,%1,%2,%3};"
        : "+f"(c[0]), "+f"(c[1]), "+f"(c[2]), "+f"(c[3])
        : "r"(a[0]), "r"(a[1]), "r"(a[2]), "r"(a[3]), "r"(b0), "r"(b1));
}
__device__ __forceinline__ void cpa(void* s, const void* g, bool v) {
    uint32_t sa = (uint32_t)__cvta_generic_to_shared(s);
    int sz = v ? 16 : 0;
    asm volatile("cp.async.cg.shared.global [%0],[%1],16,%2;" :: "r"(sa), "l"(g), "r"(sz));
}
__device__ __forceinline__ void cpcommit() { asm volatile("cp.async.commit_group;"); }
template <int N> __device__ __forceinline__ void cpwait() {
    asm volatile("cp.async.wait_group %0;" :: "n"(N));
}
__device__ __forceinline__ void redv4(float* gp, float x, float y, float z, float w) {
    asm volatile("red.global.add.v4.f32 [%0],{%1,%2,%3,%4};"
                 :: "l"(gp), "f"(x), "f"(y), "f"(z), "f"(w));
}

// smem pitches (words): A-pitch = 4 mod 32, B-pitch = 8 mod 32 -> conflict-free frags
#define PX 36
#define PW 136
#define PH 132
#define PW3 72

// ---- edge kernel smem layout (words) — X/H/M share one pool (disjoint lifetimes) ----
#define OFF_EB1 256
#define OFF_EB2 384
#define OFF_CB1 512
#define OFF_CW2 576
#define OFF_SCW 640
#define OFF_POOL 768                 // pool: 128*PH = 16896 words
#define OFF_X   OFF_POOL             // X double buffer (2*128*PX = 9216) inside pool
#define OFF_H   OFF_POOL             // H tile (written after GEMM1 completes)
#define OFF_M   OFF_POOL             // M tile (overwrites H after GEMM2 completes)
#define OFF_W   (OFF_POOL + 16896)   // W double buffer: 2*32*PW = 8704 words
#define EDGE_SMEM_WORDS (OFF_W + 8704)             // 26368
#define EDGE_SMEM_BYTES (EDGE_SMEM_WORDS * 4)      // 105472

// ---- node kernel smem layout (words) ----
#define NOFF_B1 0
#define NOFF_B2 128
#define NOFF_POOL 256
#define NOFF_X  NOFF_POOL
#define NOFF_H  NOFF_POOL
#define NOFF_W  (NOFF_POOL + 16896)
#define NODE_SMEM_WORDS (NOFF_W + 8704)            // 25856
#define NODE_SMEM_BYTES (NODE_SMEM_WORDS * 4)      // 103424

// ------------- shared GEMM chunk: one 32-wide K slab of a 128xN tile -------------
// warp layout: wm = warp&3 (rows wm*32..+31), wn = warp>>2 (N half)
template <int NT, bool CVT>
__device__ __forceinline__ void chunk_mma(
    const uint32_t* __restrict__ A, int pa, int acol,
    const uint32_t* __restrict__ W, int pw, int ncb,
    int wm, int g, int tig, float acc[2][8][4])
{
#pragma unroll
    for (int ks = 0; ks < 4; ks++) {
        uint32_t a[2][4];
#pragma unroll
        for (int mt = 0; mt < 2; mt++) {
            int r = wm * 32 + mt * 16 + g;
            const uint32_t* p0 = A + r * pa + acol + ks * 8 + tig;
            const uint32_t* p1 = A + (r + 8) * pa + acol + ks * 8 + tig;
            if (CVT) {
                a[mt][0] = f2tf(__uint_as_float(p0[0]));
                a[mt][1] = f2tf(__uint_as_float(p1[0]));
                a[mt][2] = f2tf(__uint_as_float(p0[4]));
                a[mt][3] = f2tf(__uint_as_float(p1[4]));
            } else {
                a[mt][0] = p0[0]; a[mt][1] = p1[0];
                a[mt][2] = p0[4]; a[mt][3] = p1[4];
            }
        }
        const uint32_t* b0p = W + (ks * 8 + tig) * pw + ncb + g;
        const uint32_t* b1p = W + (ks * 8 + tig + 4) * pw + ncb + g;
#pragma unroll
        for (int nt = 0; nt < NT; nt++) {
            uint32_t b0 = b0p[nt * 8], b1 = b1p[nt * 8];
            mma8(acc[0][nt], a[0], b0, b1);
            mma8(acc[1][nt], a[1], b0, b1);
        }
    }
}

__device__ __forceinline__ void zero_acc(float acc[2][8][4]) {
#pragma unroll
    for (int mt = 0; mt < 2; mt++)
#pragma unroll
        for (int nt = 0; nt < 8; nt++)
#pragma unroll
            for (int q = 0; q < 4; q++) acc[mt][nt][q] = 0.f;
}

__device__ __forceinline__ void load_w_chunk(uint32_t* wb, const uint32_t* Wg,
                                             int wcols, int pw, int kc, int tid) {
    int nv4 = wcols >> 2;
    int tot = 32 * nv4;
    for (int i = tid; i < tot; i += 256) {
        int r = i / nv4, j = i - r * nv4;
        cpa(&wb[r * pw + j * 4], &Wg[(size_t)(kc * 32 + r) * wcols + j * 4], true);
    }
}

// ------------- prep: zero accumulators, pre-convert weights + node_feat -------------
__global__ void prep_k(const float* __restrict__ nf, const float* __restrict__ eW1,
                       const float* __restrict__ eW2, const float* __restrict__ nW1,
                       const float* __restrict__ nW2, const float* __restrict__ cW1) {
    int i = blockIdx.x * 256 + threadIdx.x;
    int st = gridDim.x * 256;
    for (int j = i; j < NN * 128; j += st) { g_aggr[j] = 0.f; g_nft[j] = f2tf(nf[j]); }
    for (int j = i; j < NN * 3; j += st) g_cacc[j] = 0.f;
    for (int j = i; j < 320 * 128; j += st) g_eW1t[j] = f2tf(eW1[j]);
    for (int j = i; j < 128 * 128; j += st) { g_eW2t[j] = f2tf(eW2[j]); g_nW2t[j] = f2tf(nW2[j]); }
    for (int j = i; j < 256 * 128; j += st) g_nW1t[j] = f2tf(nW1[j]);
    for (int j = i; j < 128 * 64; j += st) g_cW1t[j] = f2tf(cW1[j]);
}

// ------------- edge kernel: fully fused edge MLP + scatter + coord head -------------
extern "C" __global__ void __launch_bounds__(256, 2)
edge_kernel(const int* __restrict__ ei, const float* __restrict__ ea,
            const float* __restrict__ coords,
            const float* __restrict__ eb1, const float* __restrict__ eb2,
            const float* __restrict__ cb1, const float* __restrict__ cw2,
            const float* __restrict__ cb2p)
{
    extern __shared__ uint32_t sm[];
    float* smf = (float*)sm;
    int* s_src = (int*)sm;
    int* s_dst = (int*)sm + 128;
    int tid = threadIdx.x;
    int e0 = blockIdx.x * 128;

    if (tid < 128) {
        s_src[tid] = ei[e0 + tid];
        s_dst[tid] = ei[NE + e0 + tid];
        smf[OFF_EB1 + tid] = eb1[tid];
        smf[OFF_EB2 + tid] = eb2[tid];
        smf[OFF_SCW + tid] = 0.f;
    }
    if (tid < 64) { smf[OFF_CB1 + tid] = cb1[tid]; smf[OFF_CW2 + tid] = cw2[tid]; }
    __syncthreads();

    int warp = tid >> 5, lane = tid & 31;
    int wm = warp & 3, wn = warp >> 2;
    int g = lane >> 2, tig = lane & 3;

    // X chunk loader: cols [0,128)=nf[src], [128,256)=nf[dst], [256,320)=edge_attr
    auto loadX = [&](int kc, int buf) {
        uint32_t* xb = sm + OFF_X + buf * (128 * PX);
#pragma unroll
        for (int q = 0; q < 4; q++) {
            int i = q * 256 + tid;
            int row = i >> 3, j = i & 7;
            const float* src;
            if (kc < 4)      src = (const float*)&g_nft[(size_t)s_src[row] * 128 + kc * 32 + j * 4];
            else if (kc < 8) src = (const float*)&g_nft[(size_t)s_dst[row] * 128 + (kc - 4) * 32 + j * 4];
            else             src = &ea[(size_t)(e0 + row) * 64 + (kc - 8) * 32 + j * 4];
            cpa(&xb[row * PX + j * 4], src, true);
        }
    };

    float acc[2][8][4];

    // ================= GEMM1: X[128,320] @ eW1 =================
    zero_acc(acc);
    loadX(0, 0); load_w_chunk(sm + OFF_W, g_eW1t, 128, PW, 0, tid); cpcommit();
    for (int kc = 0; kc < 10; kc++) {
        int cur = kc & 1;
        if (kc < 9) {
            loadX(kc + 1, cur ^ 1);
            load_w_chunk(sm + OFF_W + (cur ^ 1) * (32 * PW), g_eW1t, 128, PW, kc + 1, tid);
            cpcommit(); cpwait<1>();
        } else cpwait<0>();
        __syncthreads();
        chunk_mma<8, false>(sm + OFF_X + cur * (128 * PX), PX, 0,
                            sm + OFF_W + cur * (32 * PW), PW, wn * 64, wm, g, tig, acc);
        __syncthreads();
    }
    // epilogue1: +eb1, silu, tf32 -> H (reuses X pool; X is dead past this sync)
#pragma unroll
    for (int mt = 0; mt < 2; mt++)
#pragma unroll
        for (int nt = 0; nt < 8; nt++) {
            int r = wm * 32 + mt * 16 + g;
            int c = wn * 64 + nt * 8 + tig * 2;
            float b0 = smf[OFF_EB1 + c], b1 = smf[OFF_EB1 + c + 1];
            sm[OFF_H + r * PH + c]           = f2tf(silu(acc[mt][nt][0] + b0));
            sm[OFF_H + r * PH + c + 1]       = f2tf(silu(acc[mt][nt][1] + b1));
            sm[OFF_H + (r + 8) * PH + c]     = f2tf(silu(acc[mt][nt][2] + b0));
            sm[OFF_H + (r + 8) * PH + c + 1] = f2tf(silu(acc[mt][nt][3] + b1));
        }
    __syncthreads();

    // ================= GEMM2: H[128,128] @ eW2 =================
    zero_acc(acc);
    load_w_chunk(sm + OFF_W, g_eW2t, 128, PW, 0, tid); cpcommit();
    for (int kc = 0; kc < 4; kc++) {
        int cur = kc & 1;
        if (kc < 3) {
            load_w_chunk(sm + OFF_W + (cur ^ 1) * (32 * PW), g_eW2t, 128, PW, kc + 1, tid);
            cpcommit(); cpwait<1>();
        } else cpwait<0>();
        __syncthreads();
        chunk_mma<8, false>(sm + OFF_H, PH, kc * 32,
                            sm + OFF_W + cur * (32 * PW), PW, wn * 64, wm, g, tig, acc);
        __syncthreads();
    }
    // epilogue2: +eb2, silu -> MSG fp32 (overwrites H in place; safe after sync)
#pragma unroll
    for (int mt = 0; mt < 2; mt++)
#pragma unroll
        for (int nt = 0; nt < 8; nt++) {
            int r = wm * 32 + mt * 16 + g;
            int c = wn * 64 + nt * 8 + tig * 2;
            float b0 = smf[OFF_EB2 + c], b1 = smf[OFF_EB2 + c + 1];
            smf[OFF_M + r * PH + c]           = silu(acc[mt][nt][0] + b0);
            smf[OFF_M + r * PH + c + 1]       = silu(acc[mt][nt][1] + b1);
            smf[OFF_M + (r + 8) * PH + c]     = silu(acc[mt][nt][2] + b0);
            smf[OFF_M + (r + 8) * PH + c + 1] = silu(acc[mt][nt][3] + b1);
        }
    __syncthreads();

    // preload cW1 chunk 0 so its latency hides behind the scatter
    load_w_chunk(sm + OFF_W, g_cW1t, 64, PW3, 0, tid); cpcommit();

    // scatter messages: 16B vector reductions into g_aggr (fire-and-forget)
    for (int i = tid; i < 4096; i += 256) {
        int row = i >> 5, j = (i & 31) * 4;
        const float* mp = &smf[OFF_M + row * PH + j];
        redv4(&g_aggr[(size_t)s_dst[row] * 128 + j], mp[0], mp[1], mp[2], mp[3]);
    }

    // ================= GEMM3: MSG[128,128] @ cW1[128,64] =================
    zero_acc(acc);
    for (int kc = 0; kc < 4; kc++) {
        int cur = kc & 1;
        if (kc < 3) {
            load_w_chunk(sm + OFF_W + (cur ^ 1) * (32 * PW), g_cW1t, 64, PW3, kc + 1, tid);
            cpcommit(); cpwait<1>();
        } else cpwait<0>();
        __syncthreads();
        chunk_mma<4, true>(sm + OFF_M, PH, kc * 32,
                           sm + OFF_W + cur * (32 * PW), PW3, wn * 32, wm, g, tig, acc);
        __syncthreads();
    }
    // coord-head epilogue: cw[row] = sum_c silu(T+cb1)*cW2
    {
        float pa0 = 0.f, pa1 = 0.f, pb0 = 0.f, pb1 = 0.f;
#pragma unroll
        for (int nt = 0; nt < 4; nt++) {
            int c = wn * 32 + nt * 8 + tig * 2;
            float b0 = smf[OFF_CB1 + c], b1 = smf[OFF_CB1 + c + 1];
            float w0 = smf[OFF_CW2 + c], w1 = smf[OFF_CW2 + c + 1];
            pa0 += silu(acc[0][nt][0] + b0) * w0 + silu(acc[0][nt][1] + b1) * w1;
            pa1 += silu(acc[0][nt][2] + b0) * w0 + silu(acc[0][nt][3] + b1) * w1;
            pb0 += silu(acc[1][nt][0] + b0) * w0 + silu(acc[1][nt][1] + b1) * w1;
            pb1 += silu(acc[1][nt][2] + b0) * w0 + silu(acc[1][nt][3] + b1) * w1;
        }
#pragma unroll
        for (int off = 1; off <= 2; off <<= 1) {
            pa0 += __shfl_xor_sync(0xffffffffu, pa0, off);
            pa1 += __shfl_xor_sync(0xffffffffu, pa1, off);
            pb0 += __shfl_xor_sync(0xffffffffu, pb0, off);
            pb1 += __shfl_xor_sync(0xffffffffu, pb1, off);
        }
        if (tig == 0) {
            atomicAdd(&smf[OFF_SCW + wm * 32 + g], pa0);
            atomicAdd(&smf[OFF_SCW + wm * 32 + g + 8], pa1);
            atomicAdd(&smf[OFF_SCW + wm * 32 + 16 + g], pb0);
            atomicAdd(&smf[OFF_SCW + wm * 32 + 16 + g + 8], pb1);
        }
    }
    __syncthreads();

    // coordinate update scatter
    if (tid < 128) {
        float cw = smf[OFF_SCW + tid] + __ldg(cb2p);
        int s = s_src[tid], d = s_dst[tid];
        float dx = __ldg(&coords[s * 3 + 0]) - __ldg(&coords[d * 3 + 0]);
        float dy = __ldg(&coords[s * 3 + 1]) - __ldg(&coords[d * 3 + 1]);
        float dz = __ldg(&coords[s * 3 + 2]) - __ldg(&coords[d * 3 + 2]);
        float sc = cw / (sqrtf(dx * dx + dy * dy + dz * dz) + EPS);
        atomicAdd(&g_cacc[d * 3 + 0], sc * dx);
        atomicAdd(&g_cacc[d * 3 + 1], sc * dy);
        atomicAdd(&g_cacc[d * 3 + 2], sc * dz);
    }
}

// ------------- node kernel: node MLP + residual + coords epilogue -------------
extern "C" __global__ void __launch_bounds__(256, 2)
node_kernel(const float* __restrict__ nf, const float* __restrict__ coords,
            const float* __restrict__ nb1, const float* __restrict__ nb2,
            float* __restrict__ out)
{
    extern __shared__ uint32_t sm[];
    float* smf = (float*)sm;
    int tid = threadIdx.x;
    int n0 = blockIdx.x * 128;

    if (tid < 128) { smf[NOFF_B1 + tid] = nb1[tid]; smf[NOFF_B2 + tid] = nb2[tid]; }
    __syncthreads();

    int warp = tid >> 5, lane = tid & 31;
    int wm = warp & 3, wn = warp >> 2;
    int g = lane >> 2, tig = lane & 3;

    auto loadX = [&](int kc, int buf) {
        uint32_t* xb = sm + NOFF_X + buf * (128 * PX);
#pragma unroll
        for (int q = 0; q < 4; q++) {
            int i = q * 256 + tid;
            int row = i >> 3, j = i & 7;
            int node = n0 + row;
            bool v = node < NN;
            const float* src;
            if (kc < 4) src = (const float*)&g_nft[v ? ((size_t)node * 128 + kc * 32 + j * 4) : 0];
            else        src = &g_aggr[v ? ((size_t)node * 128 + (kc - 4) * 32 + j * 4) : 0];
            cpa(&xb[row * PX + j * 4], src, v);
        }
    };

    float acc[2][8][4];

    // GEMM1: [nf | aggr][128,256] @ nW1
    zero_acc(acc);
    loadX(0, 0); load_w_chunk(sm + NOFF_W, g_nW1t, 128, PW, 0, tid); cpcommit();
    for (int kc = 0; kc < 8; kc++) {
        int cur = kc & 1;
        if (kc < 7) {
            loadX(kc + 1, cur ^ 1);
            load_w_chunk(sm + NOFF_W + (cur ^ 1) * (32 * PW), g_nW1t, 128, PW, kc + 1, tid);
            cpcommit(); cpwait<1>();
        } else cpwait<0>();
        __syncthreads();
        chunk_mma<8, false>(sm + NOFF_X + cur * (128 * PX), PX, 0,
                            sm + NOFF_W + cur * (32 * PW), PW, wn * 64, wm, g, tig, acc);
        __syncthreads();
    }
#pragma unroll
    for (int mt = 0; mt < 2; mt++)
#pragma unroll
        for (int nt = 0; nt < 8; nt++) {
            int r = wm * 32 + mt * 16 + g;
            int c = wn * 64 + nt * 8 + tig * 2;
            float b0 = smf[NOFF_B1 + c], b1 = smf[NOFF_B1 + c + 1];
            sm[NOFF_H + r * PH + c]           = f2tf(silu(acc[mt][nt][0] + b0));
            sm[NOFF_H + r * PH + c + 1]       = f2tf(silu(acc[mt][nt][1] + b1));
            sm[NOFF_H + (r + 8) * PH + c]     = f2tf(silu(acc[mt][nt][2] + b0));
            sm[NOFF_H + (r + 8) * PH + c + 1] = f2tf(silu(acc[mt][nt][3] + b1));
        }
    __syncthreads();

    // GEMM2: H @ nW2
    zero_acc(acc);
    load_w_chunk(sm + NOFF_W, g_nW2t, 128, PW, 0, tid); cpcommit();
    for (int kc = 0; kc < 4; kc++) {
        int cur = kc & 1;
        if (kc < 3) {
            load_w_chunk(sm + NOFF_W + (cur ^ 1) * (32 * PW), g_nW2t, 128, PW, kc + 1, tid);
            cpcommit(); cpwait<1>();
        } else cpwait<0>();
        __syncthreads();
        chunk_mma<8, false>(sm + NOFF_H, PH, kc * 32,
                            sm + NOFF_W + cur * (32 * PW), PW, wn * 64, wm, g, tig, acc);
        __syncthreads();
    }
    // epilogue: residual + bias -> out nodes
#pragma unroll
    for (int mt = 0; mt < 2; mt++)
#pragma unroll
        for (int nt = 0; nt < 8; nt++) {
            int r = wm * 32 + mt * 16 + g;
            int c = wn * 64 + nt * 8 + tig * 2;
            float b0 = smf[NOFF_B2 + c], b1 = smf[NOFF_B2 + c + 1];
            int na = n0 + r, nb = n0 + r + 8;
            if (na < NN) {
                out[(size_t)na * 128 + c]     = acc[mt][nt][0] + b0 + __ldg(&nf[(size_t)na * 128 + c]);
                out[(size_t)na * 128 + c + 1] = acc[mt][nt][1] + b1 + __ldg(&nf[(size_t)na * 128 + c + 1]);
            }
            if (nb < NN) {
                out[(size_t)nb * 128 + c]     = acc[mt][nt][2] + b0 + __ldg(&nf[(size_t)nb * 128 + c]);
                out[(size_t)nb * 128 + c + 1] = acc[mt][nt][3] + b1 + __ldg(&nf[(size_t)nb * 128 + c + 1]);
            }
        }

    // coords epilogue
    for (int i = tid; i < 384; i += 256) {
        int node = n0 + i / 3, k = i % 3;
        if (node < NN)
            out[(size_t)NN * 128 + node * 3 + k] = coords[node * 3 + k] + g_cacc[node * 3 + k];
    }
}

// ------------- host entry -------------
extern "C" void kernel_launch(void* const* d_in, const int* in_sizes, int n_in,
                              void* d_out, int out_size) {
    const float* nf     = (const float*)d_in[0];
    const int*   ei     = (const int*)d_in[1];
    const float* ea     = (const float*)d_in[2];
    const float* coords = (const float*)d_in[3];
    const float* eW1 = (const float*)d_in[4];
    const float* eb1 = (const float*)d_in[5];
    const float* eW2 = (const float*)d_in[6];
    const float* eb2 = (const float*)d_in[7];
    const float* nW1 = (const float*)d_in[8];
    const float* nb1 = (const float*)d_in[9];
    const float* nW2 = (const float*)d_in[10];
    const float* nb2 = (const float*)d_in[11];
    const float* cW1 = (const float*)d_in[12];
    const float* cb1 = (const float*)d_in[13];
    const float* cW2 = (const float*)d_in[14];
    const float* cb2 = (const float*)d_in[15];
    float* out = (float*)d_out;

    cudaFuncSetAttribute(edge_kernel, cudaFuncAttributeMaxDynamicSharedMemorySize, EDGE_SMEM_BYTES);
    cudaFuncSetAttribute(node_kernel, cudaFuncAttributeMaxDynamicSharedMemorySize, NODE_SMEM_BYTES);

    prep_k<<<512, 256>>>(nf, eW1, eW2, nW1, nW2, cW1);
    edge_kernel<<<NE / 128, 256, EDGE_SMEM_BYTES>>>(ei, ea, coords, eb1, eb2, cb1, cW2, cb2);
    node_kernel<<<(NN + 127) / 128, 256, NODE_SMEM_BYTES>>>(nf, coords, nb1, nb2, out);
}